// round 15
// baseline (speedup 1.0000x reference)
#include <cuda_runtime.h>
#include <math.h>

#define Bq 4
#define Lq 4096
#define Hq 8
#define Dq 64
#define SK 9
#define U  9
#define BH (Bq*Hq)
#define NCH 8
#define CHK (Lq/NCH)    // 512 (topk chunking)
#define NCS 32
#define CHS (Lq/NCS)    // 128 (scores/attn_ctx chunking)

// scratch (static __device__ arrays — zero-initialized, no allocation)
__device__ float  g_M[BH * Lq];
__device__ int    g_top[BH * U];
__device__ float4 g_vmean4[BH * (Dq/4)];
__device__ float  g_cand_v[BH * NCH * U];
__device__ int    g_cand_i[BH * NCH * U];
__device__ int    g_cnt[BH];
__device__ int    g_cnt2[BH];
__device__ float  g_scores[BH * U * Lq];          // e = exp(s - m_chunk)
__device__ float  g_cmax[BH * NCS * U];
__device__ float  g_csum[BH * NCS * U];
__device__ float  g_part[BH * NCS * 10 * Dq];     // 9 ctx rows + vsum
__device__ float  g_ctxtop[BH * U * Dq];

// ---------------------------------------------------------------------------
// sampled scores. One warp per (b,l) covering ALL 8 heads. (LTS-bound)
// ---------------------------------------------------------------------------
__global__ void __launch_bounds__(128)
k_sample(const float* __restrict__ q,
         const float* __restrict__ k,
         const int*   __restrict__ idx,
         int woff)
{
    int warp = ((blockIdx.x * 128 + threadIdx.x) >> 5) + woff;
    int lane = threadIdx.x & 31;
    int l = warp & (Lq - 1);
    int b = warp >> 12;

    const float4* qrow = (const float4*)(q + (size_t)(b * Lq + l) * Hq * Dq);
    float4 q4[4];
#pragma unroll
    for (int r = 0; r < 4; r++) q4[r] = qrow[lane + 32 * r];

    int ks[SK];
#pragma unroll
    for (int s = 0; s < SK; s++) ks[s] = idx[l * SK + s];

    int half = lane >> 4;
    int rsel = lane & 15;

    float mx = -INFINITY, sm = 0.f;
#pragma unroll
    for (int g3 = 0; g3 < SK; g3 += 3) {
        float4 kv[3][4];
#pragma unroll
        for (int j = 0; j < 3; j++) {
            const float4* krow = (const float4*)(k + (size_t)(b * Lq + ks[g3 + j]) * Hq * Dq);
#pragma unroll
            for (int r = 0; r < 4; r++) kv[j][r] = krow[lane + 32 * r];
        }
#pragma unroll
        for (int j = 0; j < 3; j++) {
#pragma unroll
            for (int r = 0; r < 4; r++) {
                float p = kv[j][r].x * q4[r].x + kv[j][r].y * q4[r].y
                        + kv[j][r].z * q4[r].z + kv[j][r].w * q4[r].w;
                p += __shfl_xor_sync(0xffffffffu, p, 1);
                p += __shfl_xor_sync(0xffffffffu, p, 2);
                p += __shfl_xor_sync(0xffffffffu, p, 4);
                p += __shfl_xor_sync(0xffffffffu, p, 8);
                if (rsel == r) { mx = fmaxf(mx, p); sm += p; }
            }
        }
    }

    if (rsel < 4) {
        int h = 2 * rsel + half;
        g_M[(b * Hq + h) * Lq + l] = mx - sm * (1.0f / (float)Lq);
    }
}

// ---------------------------------------------------------------------------
// per-chunk top-9; last finishing block per bh merges candidates
// ---------------------------------------------------------------------------
__global__ void __launch_bounds__(128)
k_topk(int blk_off)
{
    int blk = blockIdx.x + blk_off;
    int bh = blk >> 3, ch = blk & 7;
    int base = ch * CHK;
    int t = threadIdx.x;

    __shared__ float sv[CHK];
    __shared__ float rv[128];
    __shared__ int   ri[128];

    for (int i = t; i < CHK; i += 128) sv[i] = g_M[bh * Lq + base + i];
    __syncthreads();

    for (int r = 0; r < U; r++) {
        float bv = -INFINITY; int bi = 0x7fffffff;
#pragma unroll
        for (int j = 0; j < CHK / 128; j++) {
            int i = t + j * 128;
            float vv = sv[i];
            if (vv > bv || (vv == bv && i < bi)) { bv = vv; bi = i; }
        }
        rv[t] = bv; ri[t] = bi;
        __syncthreads();
        for (int o = 64; o > 0; o >>= 1) {
            if (t < o) {
                float v2 = rv[t + o]; int i2 = ri[t + o];
                if (v2 > rv[t] || (v2 == rv[t] && i2 < ri[t])) { rv[t] = v2; ri[t] = i2; }
            }
            __syncthreads();
        }
        if (t == 0) {
            g_cand_v[blk * U + r] = rv[0];
            g_cand_i[blk * U + r] = base + ri[0];
            sv[ri[0]] = -INFINITY;
        }
        __syncthreads();
    }

    __threadfence();
    __shared__ int is_last;
    if (t == 0) is_last = (atomicAdd(&g_cnt[bh], 1) == NCH - 1);
    __syncthreads();
    if (!is_last || t >= 32) return;
    if (t == 0) g_cnt[bh] = 0;

    const int NC = NCH * U;          // 72
    float v0 = -INFINITY, v1 = -INFINITY, v2 = -INFINITY;
    int   i0 = 0x7fffffff, i1 = 0x7fffffff, i2 = 0x7fffffff;
    if (t      < NC) { v0 = g_cand_v[bh * NC + t];      i0 = g_cand_i[bh * NC + t]; }
    if (t + 32 < NC) { v1 = g_cand_v[bh * NC + t + 32]; i1 = g_cand_i[bh * NC + t + 32]; }
    if (t + 64 < NC) { v2 = g_cand_v[bh * NC + t + 64]; i2 = g_cand_i[bh * NC + t + 64]; }

    for (int r = 0; r < U; r++) {
        float bv = v0; int bi = i0;
        if (v1 > bv || (v1 == bv && i1 < bi)) { bv = v1; bi = i1; }
        if (v2 > bv || (v2 == bv && i2 < bi)) { bv = v2; bi = i2; }
#pragma unroll
        for (int o = 16; o > 0; o >>= 1) {
            float ov = __shfl_xor_sync(0xffffffffu, bv, o);
            int   oi = __shfl_xor_sync(0xffffffffu, bi, o);
            if (ov > bv || (ov == bv && oi < bi)) { bv = ov; bi = oi; }
        }
        if (t == 0) g_top[bh * U + r] = bi;
        if (i0 == bi) v0 = -INFINITY;
        if (i1 == bi) v1 = -INFINITY;
        if (i2 == bi) v2 = -INFINITY;
    }
}

// ---------------------------------------------------------------------------
// scores, shuffle-free. 128-key chunks, 128 threads, K tile in static smem.
// ---------------------------------------------------------------------------
__global__ void __launch_bounds__(128)
k_scores(const float* __restrict__ q, const float* __restrict__ k, int blk_off)
{
    __shared__ float4 sk4[128 * 17];       // 34.8KB
    __shared__ float  qr[U * Dq];          // 2.3KB
    __shared__ float  redm[4 * U];
    __shared__ float  rede[4 * U];

    int blk = blockIdx.x + blk_off;
    int bh = blk >> 5, ch = blk & 31;
    int b = bh / Hq, h = bh % Hq;
    int t = threadIdx.x;
    int w = t >> 5, lane = t & 31;

    for (int i = t; i < U * Dq; i += 128) {
        int r = i >> 6, d = i & 63;
        int l = g_top[bh * U + r];
        qr[i] = q[((size_t)(b * Lq + l) * Hq + h) * Dq + d] * 0.125f;
    }

    const float* kbase = k + ((size_t)b * Lq * Hq + h) * Dq;
    int base = ch * CHS;
#pragma unroll
    for (int i = 0; i < 16; i++) {
        int f = i * 128 + t;
        int row = f >> 4, d4 = f & 15;
        sk4[row * 17 + d4] = *(const float4*)(kbase
                              + (size_t)(base + row) * (Hq * Dq) + d4 * 4);
    }
    __syncthreads();

    const float4* qr4 = (const float4*)qr;
    float dot[U];
#pragma unroll
    for (int r = 0; r < U; r++) dot[r] = 0.f;
#pragma unroll
    for (int i = 0; i < 16; i++) {
        float4 kv = sk4[t * 17 + i];
#pragma unroll
        for (int r = 0; r < U; r++) {
            float4 qv = qr4[r * 16 + i];    // broadcast
            dot[r] += kv.x * qv.x + kv.y * qv.y + kv.z * qv.z + kv.w * qv.w;
        }
    }

#pragma unroll
    for (int r = 0; r < U; r++) {
        float m = dot[r];
#pragma unroll
        for (int o = 16; o > 0; o >>= 1) m = fmaxf(m, __shfl_xor_sync(0xffffffffu, m, o));
        if (lane == 0) redm[w * U + r] = m;
    }
    __syncthreads();
    float m_c[U];
#pragma unroll
    for (int r = 0; r < U; r++) {
        float m = redm[r];
#pragma unroll
        for (int j = 1; j < 4; j++) m = fmaxf(m, redm[j * U + r]);
        m_c[r] = m;
    }

#pragma unroll
    for (int r = 0; r < U; r++) {
        float e0 = __expf(dot[r] - m_c[r]);
        g_scores[((size_t)(bh * U + r)) * Lq + base + t] = e0;
        float e = e0;
#pragma unroll
        for (int o = 16; o > 0; o >>= 1) e += __shfl_xor_sync(0xffffffffu, e, o);
        if (lane == 0) rede[w * U + r] = e;
    }
    __syncthreads();
    if (t < U) {
        float S = 0.f;
#pragma unroll
        for (int j = 0; j < 4; j++) S += rede[j * U + t];
        g_cmax[blk * U + t] = m_c[t];
        g_csum[blk * U + t] = S;
    }
}

// ---------------------------------------------------------------------------
// attn write + ctx partials + V sum. 128-key chunks, 128 threads.
// ---------------------------------------------------------------------------
__global__ void __launch_bounds__(128)
k_attn_ctx(const float* __restrict__ v, float* __restrict__ out, int blk_off)
{
    __shared__ float sa[U * CHS];            // 1152
    __shared__ float cred[4 * 10 * Dq];      // 2560
    __shared__ float sf[U];

    int blk = blockIdx.x + blk_off;
    int bh = blk >> 5, ch = blk & 31;
    int b = bh / Hq, h = bh % Hq;
    int t = threadIdx.x;

    if (t < U) {
        float m_r = -INFINITY;
#pragma unroll
        for (int c = 0; c < NCS; c++) m_r = fmaxf(m_r, g_cmax[(bh * NCS + c) * U + t]);
        float S = 0.f;
#pragma unroll
        for (int c = 0; c < NCS; c++)
            S += g_csum[(bh * NCS + c) * U + t] * __expf(g_cmax[(bh * NCS + c) * U + t] - m_r);
        float m_c = g_cmax[(bh * NCS + ch) * U + t];
        sf[t] = __expf(m_c - m_r) / S;
    }
    __syncthreads();

    float* attn = out + (size_t)Bq * Lq * Hq * Dq + (size_t)bh * U * Lq;
    int base = ch * CHS;
#pragma unroll
    for (int r = 0; r < U; r++) {
        float a = g_scores[((size_t)(bh * U + r)) * Lq + base + t] * sf[r];
        sa[(r << 7) + t] = a;
        attn[(size_t)r * Lq + base + t] = a;
    }
    __syncthreads();

    {
        int d4 = t & 15;
        int rg = t >> 4;                 // 0..7
        float4 acc[U];
        float4 accv = make_float4(0.f, 0.f, 0.f, 0.f);
#pragma unroll
        for (int r = 0; r < U; r++) acc[r] = make_float4(0.f, 0.f, 0.f, 0.f);

#pragma unroll 4
        for (int j = rg; j < CHS; j += 8) {
            const float4* vrow = (const float4*)(v + ((size_t)(b * Lq + base + j) * Hq + h) * Dq);
            float4 vv = vrow[d4];
            accv.x += vv.x; accv.y += vv.y; accv.z += vv.z; accv.w += vv.w;
#pragma unroll
            for (int r = 0; r < U; r++) {
                float a = sa[(r << 7) + j];
                acc[r].x += a * vv.x; acc[r].y += a * vv.y;
                acc[r].z += a * vv.z; acc[r].w += a * vv.w;
            }
        }

#pragma unroll
        for (int r = 0; r < U; r++) {
            acc[r].x += __shfl_xor_sync(0xffffffffu, acc[r].x, 16);
            acc[r].y += __shfl_xor_sync(0xffffffffu, acc[r].y, 16);
            acc[r].z += __shfl_xor_sync(0xffffffffu, acc[r].z, 16);
            acc[r].w += __shfl_xor_sync(0xffffffffu, acc[r].w, 16);
        }
        accv.x += __shfl_xor_sync(0xffffffffu, accv.x, 16);
        accv.y += __shfl_xor_sync(0xffffffffu, accv.y, 16);
        accv.z += __shfl_xor_sync(0xffffffffu, accv.z, 16);
        accv.w += __shfl_xor_sync(0xffffffffu, accv.w, 16);

        int w = t >> 5;
        if ((t & 31) < 16) {
#pragma unroll
            for (int r = 0; r < U; r++)
                ((float4*)cred)[(w * 10 + r) * 16 + d4] = acc[r];
            ((float4*)cred)[(w * 10 + 9) * 16 + d4] = accv;
        }
    }
    __syncthreads();

    for (int i = t; i < 10 * Dq; i += 128) {
        int row = i >> 6, dd = i & 63;
        float s = 0.f;
#pragma unroll
        for (int w = 0; w < 4; w++) s += cred[(w * 10 + row) * Dq + dd];
        g_part[((size_t)(bh * NCS + ch) * 10 + row) * Dq + dd] = s;
    }

    __threadfence();
    __shared__ int is_last;
    if (t == 0) is_last = (atomicAdd(&g_cnt2[bh], 1) == NCS - 1);
    __syncthreads();
    if (!is_last) return;
    if (t == 0) g_cnt2[bh] = 0;

    for (int i = t; i < 10 * Dq; i += 128) {
        int row = i >> 6, dd = i & 63;
        float s = 0.f;
#pragma unroll
        for (int c = 0; c < NCS; c++)
            s += g_part[((size_t)(bh * NCS + c) * 10 + row) * Dq + dd];
        if (row < U) g_ctxtop[(bh * U + row) * Dq + dd] = s;
        else ((float*)g_vmean4)[bh * Dq + dd] = s * (1.0f / (float)Lq);
    }
}

// ---------------------------------------------------------------------------
// final context write: vmean everywhere, ctx_top at top rows
// ---------------------------------------------------------------------------
#define NBCAST ((Bq*Lq*Hq*Dq/4)/256)   // 8192

__global__ void __launch_bounds__(256)
k_bcast(float4* __restrict__ out4)
{
    int f = blockIdx.x * 256 + threadIdx.x;
    int b = f >> 19;
    int h = (f >> 4) & 7;
    int l = (f >> 7) & 4095;
    int bh = b * Hq + h;
    int rr = -1;
#pragma unroll
    for (int r = 0; r < U; r++) if (g_top[bh * U + r] == l) rr = r;
    float4 val;
    if (rr >= 0) val = ((const float4*)g_ctxtop)[(bh * U + rr) * 16 + (f & 15)];
    else         val = g_vmean4[(bh << 4) + (f & 15)];
    out4[f] = val;
}

// ---------------------------------------------------------------------------
extern "C" void kernel_launch(void* const* d_in, const int* in_sizes, int n_in,
                              void* d_out, int out_size)
{
    const float* q   = (const float*)d_in[0];
    const float* k   = (const float*)d_in[1];
    const float* v   = (const float*)d_in[2];
    const int*   idx = (const int*)d_in[3];
    float* out = (float*)d_out;

    (void)in_sizes; (void)n_in; (void)out_size;

    // two non-blocking streams + fork/join events (created once; host-side
    // resources only — no device memory)
    static cudaStream_t st[2];
    static cudaEvent_t  evFork, evJoin[2];
    static int init = 0;
    if (!init) {
        cudaStreamCreateWithFlags(&st[0], cudaStreamNonBlocking);
        cudaStreamCreateWithFlags(&st[1], cudaStreamNonBlocking);
        cudaEventCreateWithFlags(&evFork,    cudaEventDisableTiming);
        cudaEventCreateWithFlags(&evJoin[0], cudaEventDisableTiming);
        cudaEventCreateWithFlags(&evJoin[1], cudaEventDisableTiming);
        init = 1;
    }

    // fork from the (captured) legacy stream
    cudaEventRecord(evFork, 0);
    cudaStreamWaitEvent(st[0], evFork, 0);
    cudaStreamWaitEvent(st[1], evFork, 0);

    // per-half pipelines: half i handles b in {2i, 2i+1} == bh in [16i, 16i+16)
    for (int i = 0; i < 2; i++) {
        k_sample<<<(Bq * Lq) / 8, 128, 0, st[i]>>>(q, k, idx, i * (2 * Lq));
        k_topk<<<(BH / 2) * NCH, 128, 0, st[i]>>>(i * (BH / 2) * NCH);
        k_scores<<<(BH / 2) * NCS, 128, 0, st[i]>>>(q, k, i * (BH / 2) * NCS);
        k_attn_ctx<<<(BH / 2) * NCS, 128, 0, st[i]>>>(v, out, i * (BH / 2) * NCS);
    }

    // join back into the legacy stream
    cudaEventRecord(evJoin[0], st[0]);
    cudaEventRecord(evJoin[1], st[1]);
    cudaStreamWaitEvent(0, evJoin[0], 0);
    cudaStreamWaitEvent(0, evJoin[1], 0);

    k_bcast<<<NBCAST, 256>>>((float4*)out);
}